// round 1
// baseline (speedup 1.0000x reference)
#include <cuda_runtime.h>

#define FULL 0xffffffffu

constexpr int B = 4096;
constexpr int K = 64;
constexpr int L = 128;
constexpr int E_DIM = 16;

__device__ float g_loss[B];

// One 32-lane warp per batch element. Lane t owns states 2t, 2t+1; lane 31
// also carries the shadow state 64 (computed unpredicated on all lanes;
// only lane 31's copy is meaningful).
//
// Transition index order: M2M=0, M2I=1, M2D=2, I2M=3, I2I=4, D2M=5, D2D=6.

#define SUBSTEP(XC, RESCALE) do {                                              \
    /* emission select e[k][x] via predicated selects (no dynamic indexing) */ \
    float es0, es1;                                                            \
    {                                                                          \
        float ta = ((XC) & 1) ? E01 : E00;                                     \
        float tb = ((XC) & 1) ? E03 : E02;                                     \
        es0 = ((XC) & 2) ? tb : ta;                                            \
        float tc = ((XC) & 1) ? E11 : E10;                                     \
        float td = ((XC) & 1) ? E13 : E12;                                     \
        es1 = ((XC) & 2) ? td : tc;                                            \
    }                                                                          \
    /* prev[k] = Amm*fM + Aim*fI + Adm*fD   (old state) */                     \
    float prev0 = fmaf(Amm0, FM0, fmaf(Aim0, FI0, Adm0 * FD0));                \
    float prev1 = fmaf(Amm1, FM1, fmaf(Aim1, FI1, Adm1 * FD1));                \
    /* fI_new[k] = q*(A_M2I*fM + A_I2I*fI)  (q folded into Aq*) */             \
    float nFI0  = fmaf(AqMI0, FM0, AqII0 * FI0);                               \
    float nFI1  = fmaf(AqMI1, FM1, AqII1 * FI1);                               \
    float nFI64 = fmaf(Aq64MI, FM64, Aq64II * FI64);                           \
    /* fM_new[k+1] = e[k][x]*prev[k]; shift by one state via shfl */           \
    float v0 = es0 * prev0;                                                    \
    float v1 = es1 * prev1;                                                    \
    float nFM0 = __shfl_up_sync(FULL, v1, 1);                                  \
    nFM0 = (lane == 0) ? 0.0f : nFM0;     /* fM_new[0] = exp(NEG) ~= 0 */      \
    float nFM1 = v0;                                                           \
    FM64 = v1;                            /* fM_new[64] (lane 31) */           \
    FI64 = nFI64;                                                              \
    FM0 = nFM0; FM1 = nFM1; FI0 = nFI0; FI1 = nFI1;                            \
    /* delete chain on fM_new: linear recurrence -> Kogge-Stone scan */        \
    float u0 = Amd0 * FM0, u1 = Amd1 * FM1;                                    \
    float al = fmaf(Add1, u0, u1);        /* per-lane segment alpha */         \
    float t_;                                                                  \
    t_ = __shfl_up_sync(FULL, al, 1);  al = fmaf(Bp0, t_, al);                 \
    t_ = __shfl_up_sync(FULL, al, 2);  al = fmaf(Bp1, t_, al);                 \
    t_ = __shfl_up_sync(FULL, al, 4);  al = fmaf(Bp2, t_, al);                 \
    t_ = __shfl_up_sync(FULL, al, 8);  al = fmaf(Bp3, t_, al);                 \
    t_ = __shfl_up_sync(FULL, al, 16); al = fmaf(Bp4, t_, al);                 \
    float carry = __shfl_up_sync(FULL, al, 1);                                 \
    carry = (lane == 0) ? 0.0f : carry;                                        \
    FD0 = carry;                                                               \
    FD1 = fmaf(Add0, carry, u0);                                               \
    FD64 = al;                            /* fD_new[64] (lane 31) */           \
    if (RESCALE) {                                                             \
        float m = fmaxf(fmaxf(FM0, FM1), fmaxf(FI0, FI1));                     \
        m = fmaxf(m, fmaxf(FD0, FD1));                                         \
        m = fmaxf(m, fmaxf(FM64, FI64));                                       \
        m = fmaxf(m, __shfl_xor_sync(FULL, m, 16));                            \
        m = fmaxf(m, __shfl_xor_sync(FULL, m, 8));                             \
        m = fmaxf(m, __shfl_xor_sync(FULL, m, 4));                             \
        m = fmaxf(m, __shfl_xor_sync(FULL, m, 2));                             \
        m = fmaxf(m, __shfl_xor_sync(FULL, m, 1));                             \
        int ex = (int)((__float_as_uint(m) >> 23) & 255) - 127;                \
        float scale = __uint_as_float((unsigned)(127 - ex) << 23);             \
        FM0 *= scale; FM1 *= scale; FI0 *= scale; FI1 *= scale;                \
        FD0 *= scale; FD1 *= scale;                                            \
        FM64 *= scale; FI64 *= scale; FD64 *= scale;                           \
        ex_sum += ex;                                                          \
    }                                                                          \
} while (0)

__global__ __launch_bounds__(128) void phmm_kernel(
    const int*   __restrict__ x,
    const float* __restrict__ a,
    const float* __restrict__ e,
    const float* __restrict__ mus,
    const float* __restrict__ lvs)
{
    const int warp = (blockIdx.x * blockDim.x + threadIdx.x) >> 5;
    const int lane = threadIdx.x & 31;
    const int b = warp;

    const float* ab = a + (size_t)b * (K + 1) * 7;
    const int k0 = lane * 2, k1 = k0 + 1;
    const float* a0 = ab + k0 * 7;
    const float* a1 = ab + k1 * 7;

    // exp() all transitions once; fold LOG_Q (q = 0.25) into the I-pipe.
    float Amm0 = __expf(a0[0]), Amm1 = __expf(a1[0]);
    float AqMI0 = 0.25f * __expf(a0[1]), AqMI1 = 0.25f * __expf(a1[1]);
    float Amd0 = __expf(a0[2]), Amd1 = __expf(a1[2]);
    float Aim0 = __expf(a0[3]), Aim1 = __expf(a1[3]);
    float AqII0 = 0.25f * __expf(a0[4]), AqII1 = 0.25f * __expf(a1[4]);
    float Adm0 = __expf(a0[5]), Adm1 = __expf(a1[5]);
    float Add0 = __expf(a0[6]), Add1 = __expf(a1[6]);

    const float* a64 = ab + K * 7;        // state 64 (broadcast load)
    float A64mm  = __expf(a64[0]);
    float Aq64MI = 0.25f * __expf(a64[1]);
    float A64im  = __expf(a64[3]);
    float Aq64II = 0.25f * __expf(a64[4]);
    float A64dm  = __expf(a64[5]);

    const float4* e4 = (const float4*)(e + (size_t)b * K * 4);
    float4 ea = e4[k0], ebv = e4[k1];
    float E00 = __expf(ea.x),  E01 = __expf(ea.y),  E02 = __expf(ea.z),  E03 = __expf(ea.w);
    float E10 = __expf(ebv.x), E11 = __expf(ebv.y), E12 = __expf(ebv.z), E13 = __expf(ebv.w);

    // Time-invariant scan weights for the Kogge-Stone chain scan.
    // Bp[m] = product of per-lane betas over the 2^m lanes ending at this lane,
    // zeroed when out of range so the scan body is an unpredicated FMA.
    float segB = Add0 * Add1;
    float Bp0 = (lane >= 1) ? segB : 0.0f;
    { float o = __shfl_up_sync(FULL, segB, 1);  if (lane >= 1)  segB *= o; }
    float Bp1 = (lane >= 2) ? segB : 0.0f;
    { float o = __shfl_up_sync(FULL, segB, 2);  if (lane >= 2)  segB *= o; }
    float Bp2 = (lane >= 4) ? segB : 0.0f;
    { float o = __shfl_up_sync(FULL, segB, 4);  if (lane >= 4)  segB *= o; }
    float Bp3 = (lane >= 8) ? segB : 0.0f;
    { float o = __shfl_up_sync(FULL, segB, 8);  if (lane >= 8)  segB *= o; }
    float Bp4 = (lane >= 16) ? segB : 0.0f;

    // Linear-space init: fM0[0]=1, rest 0; fI=0; fD from the chain.
    float FM0 = (lane == 0) ? 1.0f : 0.0f;
    float FM1 = 0.0f;
    float FI0 = 0.0f, FI1 = 0.0f;
    float FM64 = 0.0f, FI64 = 0.0f, FD64 = 0.0f;
    float FD0, FD1;
    {
        float u0 = Amd0 * FM0, u1 = Amd1 * FM1;
        float al = fmaf(Add1, u0, u1);
        float t_;
        t_ = __shfl_up_sync(FULL, al, 1);  al = fmaf(Bp0, t_, al);
        t_ = __shfl_up_sync(FULL, al, 2);  al = fmaf(Bp1, t_, al);
        t_ = __shfl_up_sync(FULL, al, 4);  al = fmaf(Bp2, t_, al);
        t_ = __shfl_up_sync(FULL, al, 8);  al = fmaf(Bp3, t_, al);
        t_ = __shfl_up_sync(FULL, al, 16); al = fmaf(Bp4, t_, al);
        float carry = __shfl_up_sync(FULL, al, 1);
        carry = (lane == 0) ? 0.0f : carry;
        FD0 = carry;
        FD1 = fmaf(Add0, carry, u0);
        FD64 = al;
    }

    // Preload this batch's full symbol sequence: lane t holds x[4t..4t+3].
    const int4 xv = ((const int4*)(x + (size_t)b * L))[lane];
    int ex_sum = 0;

    #pragma unroll 1
    for (int l0 = 0; l0 < L / 4; ++l0) {
        int xa = __shfl_sync(FULL, xv.x, l0);
        int xb = __shfl_sync(FULL, xv.y, l0);
        int xc = __shfl_sync(FULL, xv.z, l0);
        int xd = __shfl_sync(FULL, xv.w, l0);
        SUBSTEP(xa, false);
        SUBSTEP(xb, true);
        SUBSTEP(xc, false);
        SUBSTEP(xd, true);
    }

    // KLD on lanes 0..15, reduced across the warp.
    float kt = 0.0f;
    if (lane < E_DIM) {
        float mu = mus[(size_t)b * E_DIM + lane];
        float lv = lvs[(size_t)b * E_DIM + lane];
        kt = 1.0f + lv - mu * mu - __expf(lv);
    }
    kt += __shfl_xor_sync(FULL, kt, 16);
    kt += __shfl_xor_sync(FULL, kt, 8);
    kt += __shfl_xor_sync(FULL, kt, 4);
    kt += __shfl_xor_sync(FULL, kt, 2);
    kt += __shfl_xor_sync(FULL, kt, 1);
    float kld = -0.5f * kt;

    if (lane == 31) {
        float fin = fmaf(A64mm, FM64, fmaf(A64im, FI64, A64dm * FD64));
        float loss = -(logf(fin) + (float)ex_sum * 0.69314718055994531f);
        g_loss[b] = loss + kld;
    }
}

__global__ void reduce_kernel(float* __restrict__ out)
{
    __shared__ float s[1024];
    int t = threadIdx.x;
    float v = g_loss[t] + g_loss[t + 1024] + g_loss[t + 2048] + g_loss[t + 3072];
    s[t] = v;
    __syncthreads();
    #pragma unroll
    for (int d = 512; d >= 1; d >>= 1) {
        if (t < d) s[t] += s[t + d];
        __syncthreads();
    }
    if (t == 0) out[0] = s[0] * (1.0f / (float)B);
}

extern "C" void kernel_launch(void* const* d_in, const int* in_sizes, int n_in,
                              void* d_out, int out_size)
{
    const int*   x   = (const int*)d_in[0];
    const float* a   = (const float*)d_in[1];
    const float* e   = (const float*)d_in[2];
    const float* mus = (const float*)d_in[3];
    const float* lvs = (const float*)d_in[4];

    // 4096 warps, 4 warps per block.
    phmm_kernel<<<B / 4, 128>>>(x, a, e, mus, lvs);
    reduce_kernel<<<1, 1024>>>((float*)d_out);
}

// round 2
// speedup vs baseline: 1.1065x; 1.1065x over previous
#include <cuda_runtime.h>

#define FULL 0xffffffffu

constexpr int B = 4096;
constexpr int K = 64;
constexpr int L = 128;
constexpr int E_DIM = 16;

__device__ float g_loss[B];
__device__ unsigned g_ctr = 0;

typedef unsigned long long u64;

__device__ __forceinline__ u64 pk(float lo, float hi) {
    u64 r; asm("mov.b64 %0,{%1,%2};" : "=l"(r) : "f"(lo), "f"(hi)); return r;
}
__device__ __forceinline__ void upk(u64 v, float& lo, float& hi) {
    asm("mov.b64 {%0,%1},%2;" : "=f"(lo), "=f"(hi) : "l"(v));
}
__device__ __forceinline__ u64 fma2(u64 a, u64 b, u64 c) {
    u64 d; asm("fma.rn.f32x2 %0,%1,%2,%3;" : "=l"(d) : "l"(a), "l"(b), "l"(c)); return d;
}
__device__ __forceinline__ u64 mul2(u64 a, u64 b) {
    u64 d; asm("mul.rn.f32x2 %0,%1,%2;" : "=l"(d) : "l"(a), "l"(b)); return d;
}

// One warp per batch element. Lane t owns states {2t, 2t+1} kept packed in
// f32x2 pairs; lane 31 also shadows state 64 (computed unpredicated).
// Transition order: M2M=0, M2I=1, M2D=2, I2M=3, I2I=4, D2M=5, D2D=6.

#define SUBSTEP(XC, RESCALE) do {                                              \
    u64 es = ep[(XC)];                          /* LDS.64 emission pair */     \
    u64 prev = fma2(Amm2, FMp, fma2(Aim2, FIp, mul2(Adm2, FDp)));              \
    u64 nFI  = fma2(AqMI2, FMp, mul2(AqII2, FIp));                             \
    float nFI64 = fmaf(Aq64MI, FM64, Aq64II * FI64);                           \
    u64 v = mul2(es, prev);                                                    \
    float v0, v1; upk(v, v0, v1);                                              \
    float nFM0 = __shfl_up_sync(FULL, v1, 1);                                  \
    nFM0 = (lane == 0) ? 0.0f : nFM0;                                          \
    FM64 = v1; FI64 = nFI64;                                                   \
    FMp = pk(nFM0, v0); FIp = nFI;                                             \
    /* delete chain: Kogge-Stone scan with precomputed weights */              \
    u64 u = mul2(Amd2, FMp);                                                   \
    float u0, u1; upk(u, u0, u1);                                              \
    float al = fmaf(Add1, u0, u1);                                             \
    float t_;                                                                  \
    t_ = __shfl_up_sync(FULL, al, 1);  al = fmaf(Bp0, t_, al);                 \
    t_ = __shfl_up_sync(FULL, al, 2);  al = fmaf(Bp1, t_, al);                 \
    t_ = __shfl_up_sync(FULL, al, 4);  al = fmaf(Bp2, t_, al);                 \
    t_ = __shfl_up_sync(FULL, al, 8);  al = fmaf(Bp3, t_, al);                 \
    t_ = __shfl_up_sync(FULL, al, 16); al = fmaf(Bp4, t_, al);                 \
    float carry = __shfl_up_sync(FULL, al, 1);                                 \
    carry = (lane == 0) ? 0.0f : carry;                                        \
    FDp = pk(carry, fmaf(Add0, carry, u0));                                    \
    FD64 = al;                                                                 \
    if (RESCALE) {                                                             \
        float f0, f1, g0, g1, h0, h1;                                          \
        upk(FMp, f0, f1); upk(FIp, g0, g1); upk(FDp, h0, h1);                  \
        float m = fmaxf(fmaxf(f0, f1), fmaxf(g0, g1));                         \
        m = fmaxf(m, fmaxf(h0, h1));                                           \
        m = fmaxf(m, fmaxf(FM64, FI64));                                       \
        m = fmaxf(m, FD64);                                                    \
        m = fmaxf(m, __shfl_xor_sync(FULL, m, 16));                            \
        m = fmaxf(m, __shfl_xor_sync(FULL, m, 8));                             \
        m = fmaxf(m, __shfl_xor_sync(FULL, m, 4));                             \
        m = fmaxf(m, __shfl_xor_sync(FULL, m, 2));                             \
        m = fmaxf(m, __shfl_xor_sync(FULL, m, 1));                             \
        int ex = (int)((__float_as_uint(m) >> 23) & 255) - 127;                \
        float scale = __uint_as_float((unsigned)(127 - ex) << 23);             \
        u64 s2 = pk(scale, scale);                                             \
        FMp = mul2(FMp, s2); FIp = mul2(FIp, s2); FDp = mul2(FDp, s2);         \
        FM64 *= scale; FI64 *= scale; FD64 *= scale;                           \
        ex_sum += ex;                                                          \
    }                                                                          \
} while (0)

__global__ __launch_bounds__(128, 7) void phmm_kernel(
    const int*   __restrict__ x,
    const float* __restrict__ a,
    const float* __restrict__ e,
    const float* __restrict__ mus,
    const float* __restrict__ lvs,
    float*       __restrict__ out)
{
    const int warp = (blockIdx.x * blockDim.x + threadIdx.x) >> 5;
    const int lane = threadIdx.x & 31;
    const int wIn  = threadIdx.x >> 5;
    const int b = warp;

    __shared__ u64 sh_e[4 * 32 * 4];   // per-lane 4-symbol packed emission LUT
    __shared__ float sw[4];
    __shared__ unsigned s_rank;

    const float* ab = a + (size_t)b * (K + 1) * 7;
    const int k0 = lane * 2, k1 = k0 + 1;
    const float* a0 = ab + k0 * 7;
    const float* a1 = ab + k1 * 7;

    // exp() all transitions once; fold q = 0.25 into the I-pipe. Packed pairs.
    u64 Amm2  = pk(__expf(a0[0]), __expf(a1[0]));
    u64 AqMI2 = pk(0.25f * __expf(a0[1]), 0.25f * __expf(a1[1]));
    float Amd0 = __expf(a0[2]), Amd1 = __expf(a1[2]);
    u64 Amd2  = pk(Amd0, Amd1);
    u64 Aim2  = pk(__expf(a0[3]), __expf(a1[3]));
    u64 AqII2 = pk(0.25f * __expf(a0[4]), 0.25f * __expf(a1[4]));
    u64 Adm2  = pk(__expf(a0[5]), __expf(a1[5]));
    float Add0 = __expf(a0[6]), Add1 = __expf(a1[6]);

    const float* a64 = ab + K * 7;    // state 64 (broadcast load)
    float A64mm  = __expf(a64[0]);
    float Aq64MI = 0.25f * __expf(a64[1]);
    float A64im  = __expf(a64[3]);
    float Aq64II = 0.25f * __expf(a64[4]);
    float A64dm  = __expf(a64[5]);

    // Emission LUT into shared: ep[c] = pack(exp(e[k0][c]), exp(e[k1][c]))
    const float4* e4 = (const float4*)(e + (size_t)b * K * 4);
    float4 ea = e4[k0], ebv = e4[k1];
    u64* ep = sh_e + (size_t)(wIn * 32 + lane) * 4;
    ep[0] = pk(__expf(ea.x), __expf(ebv.x));
    ep[1] = pk(__expf(ea.y), __expf(ebv.y));
    ep[2] = pk(__expf(ea.z), __expf(ebv.z));
    ep[3] = pk(__expf(ea.w), __expf(ebv.w));

    // Time-invariant Kogge-Stone scan weights (zeroed out-of-range lanes).
    float segB = Add0 * Add1;
    float Bp0 = (lane >= 1) ? segB : 0.0f;
    { float o = __shfl_up_sync(FULL, segB, 1);  if (lane >= 1)  segB *= o; }
    float Bp1 = (lane >= 2) ? segB : 0.0f;
    { float o = __shfl_up_sync(FULL, segB, 2);  if (lane >= 2)  segB *= o; }
    float Bp2 = (lane >= 4) ? segB : 0.0f;
    { float o = __shfl_up_sync(FULL, segB, 4);  if (lane >= 4)  segB *= o; }
    float Bp3 = (lane >= 8) ? segB : 0.0f;
    { float o = __shfl_up_sync(FULL, segB, 8);  if (lane >= 8)  segB *= o; }
    float Bp4 = (lane >= 16) ? segB : 0.0f;

    // Linear-space init: fM[0]=1, rest 0; fI=0; fD from the chain.
    float FM64 = 0.0f, FI64 = 0.0f, FD64 = 0.0f;
    u64 FMp = pk((lane == 0) ? 1.0f : 0.0f, 0.0f);
    u64 FIp = pk(0.0f, 0.0f);
    u64 FDp;
    {
        float fm0, fm1; upk(FMp, fm0, fm1);
        float u0 = Amd0 * fm0, u1 = Amd1 * fm1;
        float al = fmaf(Add1, u0, u1);
        float t_;
        t_ = __shfl_up_sync(FULL, al, 1);  al = fmaf(Bp0, t_, al);
        t_ = __shfl_up_sync(FULL, al, 2);  al = fmaf(Bp1, t_, al);
        t_ = __shfl_up_sync(FULL, al, 4);  al = fmaf(Bp2, t_, al);
        t_ = __shfl_up_sync(FULL, al, 8);  al = fmaf(Bp3, t_, al);
        t_ = __shfl_up_sync(FULL, al, 16); al = fmaf(Bp4, t_, al);
        float carry = __shfl_up_sync(FULL, al, 1);
        carry = (lane == 0) ? 0.0f : carry;
        FDp = pk(carry, fmaf(Add0, carry, u0));
        FD64 = al;
    }

    // Preload symbol sequence: lane t holds x[4t..4t+3].
    const int4 xv = ((const int4*)(x + (size_t)b * L))[lane];
    int ex_sum = 0;

    __syncthreads();   // emission LUT visible

    #pragma unroll 1
    for (int l0 = 0; l0 < L / 4; ++l0) {
        int xa = __shfl_sync(FULL, xv.x, l0);
        int xb = __shfl_sync(FULL, xv.y, l0);
        int xc = __shfl_sync(FULL, xv.z, l0);
        int xd = __shfl_sync(FULL, xv.w, l0);
        SUBSTEP(xa, false);
        SUBSTEP(xb, false);
        SUBSTEP(xc, false);
        SUBSTEP(xd, true);
    }

    // KLD on lanes 0..15, reduced across the warp.
    float kt = 0.0f;
    if (lane < E_DIM) {
        float mu = mus[(size_t)b * E_DIM + lane];
        float lv = lvs[(size_t)b * E_DIM + lane];
        kt = 1.0f + lv - mu * mu - __expf(lv);
    }
    kt += __shfl_xor_sync(FULL, kt, 16);
    kt += __shfl_xor_sync(FULL, kt, 8);
    kt += __shfl_xor_sync(FULL, kt, 4);
    kt += __shfl_xor_sync(FULL, kt, 2);
    kt += __shfl_xor_sync(FULL, kt, 1);
    float kld = -0.5f * kt;

    if (lane == 31) {
        float fin = fmaf(A64mm, FM64, fmaf(A64im, FI64, A64dm * FD64));
        float loss = -(logf(fin) + (float)ex_sum * 0.69314718055994531f);
        g_loss[b] = loss + kld;
    }

    // ── Fused deterministic final reduction (last-block-done) ──
    __threadfence();
    __syncthreads();
    if (threadIdx.x == 0) s_rank = atomicAdd(&g_ctr, 1);
    __syncthreads();
    if (s_rank == gridDim.x - 1) {
        __threadfence();
        float v = 0.0f;
        #pragma unroll
        for (int i = 0; i < B / 128; ++i)
            v += __ldcg(&g_loss[threadIdx.x + i * 128]);
        v += __shfl_xor_sync(FULL, v, 16);
        v += __shfl_xor_sync(FULL, v, 8);
        v += __shfl_xor_sync(FULL, v, 4);
        v += __shfl_xor_sync(FULL, v, 2);
        v += __shfl_xor_sync(FULL, v, 1);
        if (lane == 0) sw[wIn] = v;
        __syncthreads();
        if (threadIdx.x == 0) {
            out[0] = (sw[0] + sw[1] + sw[2] + sw[3]) * (1.0f / (float)B);
            g_ctr = 0;   // reset for next graph replay
        }
    }
}

extern "C" void kernel_launch(void* const* d_in, const int* in_sizes, int n_in,
                              void* d_out, int out_size)
{
    const int*   x   = (const int*)d_in[0];
    const float* a   = (const float*)d_in[1];
    const float* e   = (const float*)d_in[2];
    const float* mus = (const float*)d_in[3];
    const float* lvs = (const float*)d_in[4];

    phmm_kernel<<<B / 4, 128>>>(x, a, e, mus, lvs, (float*)d_out);
}

// round 3
// speedup vs baseline: 1.3234x; 1.1961x over previous
#include <cuda_runtime.h>

#define FULL 0xffffffffu

constexpr int B = 4096;
constexpr int K = 64;
constexpr int L = 128;
constexpr int E_DIM = 16;

__device__ float g_loss[B];
__device__ unsigned g_ctr = 0;

typedef unsigned long long u64;

__device__ __forceinline__ u64 pk(float lo, float hi) {
    u64 r; asm("mov.b64 %0,{%1,%2};" : "=l"(r) : "f"(lo), "f"(hi)); return r;
}
__device__ __forceinline__ void upk(u64 v, float& lo, float& hi) {
    asm("mov.b64 {%0,%1},%2;" : "=f"(lo), "=f"(hi) : "l"(v));
}
__device__ __forceinline__ u64 fma2(u64 a, u64 b, u64 c) {
    u64 d; asm("fma.rn.f32x2 %0,%1,%2,%3;" : "=l"(d) : "l"(a), "l"(b), "l"(c)); return d;
}
__device__ __forceinline__ u64 mul2(u64 a, u64 b) {
    u64 d; asm("mul.rn.f32x2 %0,%1,%2;" : "=l"(d) : "l"(a), "l"(b)); return d;
}

// Two batch elements per warp: lanes 0-15 -> batch 2w, lanes 16-31 -> 2w+1.
// Within a half, lane h owns states {4h..4h+3} as two f32x2 pairs; lane 15 of
// each half also shadows state 64 (all lanes compute a shadow, unpredicated).
// Transition order: M2M=0, M2I=1, M2D=2, I2M=3, I2I=4, D2M=5, D2D=6.

#define SUBSTEP(XC, RESCALE) do {                                              \
    float4 ev = epb[(XC) * 16 + h];            /* conflict-free LDS.128 */     \
    u64 es_a = pk(ev.x, ev.y);                                                 \
    u64 es_b = pk(ev.z, ev.w);                                                 \
    u64 prev_a = fma2(Amm_a, FMa, fma2(Aim_a, FIa, mul2(Adm_a, FDa)));         \
    u64 prev_b = fma2(Amm_b, FMb, fma2(Aim_b, FIb, mul2(Adm_b, FDb)));         \
    u64 nFIa = fma2(AqMI_a, FMa, mul2(AqII_a, FIa));                           \
    u64 nFIb = fma2(AqMI_b, FMb, mul2(AqII_b, FIb));                           \
    float nFI64 = fmaf(Aq64MI, FM64, Aq64II * FI64);                           \
    u64 va = mul2(es_a, prev_a);                                               \
    u64 vb = mul2(es_b, prev_b);                                               \
    float v0, v1, v2, v3; upk(va, v0, v1); upk(vb, v2, v3);                    \
    float pv3 = __shfl_up_sync(FULL, v3, 1, 16);                               \
    float nFM0 = (h == 0) ? 0.0f : pv3;                                        \
    FM64 = v3; FI64 = nFI64;                                                   \
    FMa = pk(nFM0, v0); FMb = pk(v1, v2);                                      \
    FIa = nFIa; FIb = nFIb;                                                    \
    u64 ua = mul2(Amd_a, FMa);                                                 \
    u64 ub = mul2(Amd_b, FMb);                                                 \
    float u0, u1, u2, u3; upk(ua, u0, u1); upk(ub, u2, u3);                    \
    float al = fmaf(c2, u2, u3); al = fmaf(c1, u1, al); al = fmaf(c0, u0, al); \
    float t_;                                                                  \
    t_ = __shfl_up_sync(FULL, al, 1, 16); al = fmaf(Bp0, t_, al);              \
    t_ = __shfl_up_sync(FULL, al, 2, 16); al = fmaf(Bp1, t_, al);              \
    t_ = __shfl_up_sync(FULL, al, 4, 16); al = fmaf(Bp2, t_, al);              \
    t_ = __shfl_up_sync(FULL, al, 8, 16); al = fmaf(Bp3, t_, al);              \
    float carry = __shfl_up_sync(FULL, al, 1, 16);                             \
    carry = (h == 0) ? 0.0f : carry;                                           \
    float fd0 = carry;                                                         \
    float fd1 = fmaf(Add0, fd0, u0);                                           \
    float fd2 = fmaf(Add1, fd1, u1);                                           \
    float fd3 = fmaf(Add2, fd2, u2);                                           \
    FDa = pk(fd0, fd1); FDb = pk(fd2, fd3);                                    \
    FD64 = al;                                                                 \
    if (RESCALE) {                                                             \
        float f0, f1, f2, f3, g0, g1, g2, g3;                                  \
        upk(FMa, f0, f1); upk(FMb, f2, f3);                                    \
        upk(FIa, g0, g1); upk(FIb, g2, g3);                                    \
        float m = fmaxf(fmaxf(f0, f1), fmaxf(f2, f3));                         \
        m = fmaxf(m, fmaxf(fmaxf(g0, g1), fmaxf(g2, g3)));                     \
        m = fmaxf(m, fmaxf(fmaxf(fd0, fd1), fmaxf(fd2, fd3)));                 \
        m = fmaxf(m, fmaxf(FM64, FI64)); m = fmaxf(m, FD64);                   \
        m = fmaxf(m, __shfl_xor_sync(FULL, m, 8, 16));                         \
        m = fmaxf(m, __shfl_xor_sync(FULL, m, 4, 16));                         \
        m = fmaxf(m, __shfl_xor_sync(FULL, m, 2, 16));                         \
        m = fmaxf(m, __shfl_xor_sync(FULL, m, 1, 16));                         \
        int ex = (int)((__float_as_uint(m) >> 23) & 255) - 127;                \
        float scale = __uint_as_float((unsigned)(127 - ex) << 23);             \
        u64 s2 = pk(scale, scale);                                             \
        FMa = mul2(FMa, s2); FMb = mul2(FMb, s2);                              \
        FIa = mul2(FIa, s2); FIb = mul2(FIb, s2);                              \
        FDa = mul2(FDa, s2); FDb = mul2(FDb, s2);                              \
        FM64 *= scale; FI64 *= scale; FD64 *= scale;                           \
        ex_sum += ex;                                                          \
    }                                                                          \
} while (0)

__global__ __launch_bounds__(128) void phmm_kernel(
    const int*   __restrict__ x,
    const float* __restrict__ a,
    const float* __restrict__ e,
    const float* __restrict__ mus,
    const float* __restrict__ lvs,
    float*       __restrict__ out)
{
    const int warp = (blockIdx.x * blockDim.x + threadIdx.x) >> 5;
    const int lane = threadIdx.x & 31;
    const int half = lane >> 4;
    const int h    = lane & 15;
    const int wIn  = threadIdx.x >> 5;
    const int b = 2 * warp + half;

    __shared__ float4 sh_e[4 * 2 * 4 * 16];  // [warpInBlk][half][symbol][hlane]
    __shared__ float sw[4];
    __shared__ unsigned s_rank;

    const float* ab = a + (size_t)b * (K + 1) * 7;
    const int k0 = 4 * h;
    const float* A0 = ab + (k0 + 0) * 7;
    const float* A1 = ab + (k0 + 1) * 7;
    const float* A2 = ab + (k0 + 2) * 7;
    const float* A3 = ab + (k0 + 3) * 7;

    u64 Amm_a  = pk(__expf(A0[0]), __expf(A1[0]));
    u64 Amm_b  = pk(__expf(A2[0]), __expf(A3[0]));
    u64 AqMI_a = pk(0.25f * __expf(A0[1]), 0.25f * __expf(A1[1]));
    u64 AqMI_b = pk(0.25f * __expf(A2[1]), 0.25f * __expf(A3[1]));
    float Amd0 = __expf(A0[2]), Amd1 = __expf(A1[2]);
    float Amd2v = __expf(A2[2]), Amd3v = __expf(A3[2]);
    u64 Amd_a  = pk(Amd0, Amd1);
    u64 Amd_b  = pk(Amd2v, Amd3v);
    u64 Aim_a  = pk(__expf(A0[3]), __expf(A1[3]));
    u64 Aim_b  = pk(__expf(A2[3]), __expf(A3[3]));
    u64 AqII_a = pk(0.25f * __expf(A0[4]), 0.25f * __expf(A1[4]));
    u64 AqII_b = pk(0.25f * __expf(A2[4]), 0.25f * __expf(A3[4]));
    u64 Adm_a  = pk(__expf(A0[5]), __expf(A1[5]));
    u64 Adm_b  = pk(__expf(A2[5]), __expf(A3[5]));
    float Add0 = __expf(A0[6]), Add1 = __expf(A1[6]);
    float Add2 = __expf(A2[6]), Add3 = __expf(A3[6]);

    // Segment-alpha weights: alpha = c0*u0 + c1*u1 + c2*u2 + u3
    float c2 = Add3;
    float c1 = Add3 * Add2;
    float c0 = c1 * Add1;
    float segB = c0 * Add0;   // product of all 4 betas in this lane's segment

    const float* a64 = ab + K * 7;   // state 64 (uniform within half)
    float A64mm  = __expf(a64[0]);
    float Aq64MI = 0.25f * __expf(a64[1]);
    float A64im  = __expf(a64[3]);
    float Aq64II = 0.25f * __expf(a64[4]);
    float A64dm  = __expf(a64[5]);

    // Emission LUT, transposed for conflict-free LDS.128:
    // epb[c*16 + h] = {exp(e[4h][c]), exp(e[4h+1][c]), exp(e[4h+2][c]), exp(e[4h+3][c])}
    const float4* e4 = (const float4*)(e + (size_t)b * K * 4);
    float4 e0 = e4[k0], e1 = e4[k0 + 1], e2 = e4[k0 + 2], e3 = e4[k0 + 3];
    float4* epb = sh_e + (size_t)((wIn * 2 + half) * 4) * 16;
    epb[0 * 16 + h] = make_float4(__expf(e0.x), __expf(e1.x), __expf(e2.x), __expf(e3.x));
    epb[1 * 16 + h] = make_float4(__expf(e0.y), __expf(e1.y), __expf(e2.y), __expf(e3.y));
    epb[2 * 16 + h] = make_float4(__expf(e0.z), __expf(e1.z), __expf(e2.z), __expf(e3.z));
    epb[3 * 16 + h] = make_float4(__expf(e0.w), __expf(e1.w), __expf(e2.w), __expf(e3.w));

    // Time-invariant Kogge-Stone weights over the 16-lane segment.
    float Bp0, Bp1, Bp2, Bp3;
    {
        float Bacc = segB;
        Bp0 = (h >= 1) ? Bacc : 0.0f;
        float o = __shfl_up_sync(FULL, Bacc, 1, 16); if (h >= 1) Bacc *= o;
        Bp1 = (h >= 2) ? Bacc : 0.0f;
        o = __shfl_up_sync(FULL, Bacc, 2, 16); if (h >= 2) Bacc *= o;
        Bp2 = (h >= 4) ? Bacc : 0.0f;
        o = __shfl_up_sync(FULL, Bacc, 4, 16); if (h >= 4) Bacc *= o;
        Bp3 = (h >= 8) ? Bacc : 0.0f;
    }

    // Linear-space init: fM[0]=1, rest 0; fI=0; fD via the chain.
    u64 FMa = pk((h == 0) ? 1.0f : 0.0f, 0.0f);
    u64 FMb = pk(0.0f, 0.0f);
    u64 FIa = pk(0.0f, 0.0f), FIb = pk(0.0f, 0.0f);
    float FM64 = 0.0f, FI64 = 0.0f, FD64 = 0.0f;
    u64 FDa, FDb;
    {
        float fm0 = (h == 0) ? 1.0f : 0.0f;
        float u0 = Amd0 * fm0;            // u1..u3 = 0 at init
        float al = c0 * u0;
        float t_;
        t_ = __shfl_up_sync(FULL, al, 1, 16); al = fmaf(Bp0, t_, al);
        t_ = __shfl_up_sync(FULL, al, 2, 16); al = fmaf(Bp1, t_, al);
        t_ = __shfl_up_sync(FULL, al, 4, 16); al = fmaf(Bp2, t_, al);
        t_ = __shfl_up_sync(FULL, al, 8, 16); al = fmaf(Bp3, t_, al);
        float carry = __shfl_up_sync(FULL, al, 1, 16);
        if (h == 0) carry = 0.0f;
        float fd0 = carry;
        float fd1 = fmaf(Add0, fd0, u0);
        float fd2 = Add1 * fd1;
        float fd3 = Add2 * fd2;
        FDa = pk(fd0, fd1); FDb = pk(fd2, fd3);
        FD64 = al;
    }

    // Symbols: pack 4 × 2-bit per lane; hlane h holds x[4h..4h+3] and x[64+4h..].
    const int4* x4 = (const int4*)(x + (size_t)b * L);
    int4 xi0 = x4[h], xi1 = x4[h + 16];
    int xp0 = xi0.x | (xi0.y << 2) | (xi0.z << 4) | (xi0.w << 6);
    int xp1 = xi1.x | (xi1.y << 2) | (xi1.z << 4) | (xi1.w << 6);

    int ex_sum = 0;
    __syncthreads();   // emission LUT visible

    #pragma unroll 1
    for (int it = 0; it < 32; ++it) {
        int src = (it < 16) ? xp0 : xp1;
        int xs = __shfl_sync(FULL, src, it & 15, 16);
        SUBSTEP(xs & 3, false);
        SUBSTEP((xs >> 2) & 3, false);
        SUBSTEP((xs >> 4) & 3, false);
        SUBSTEP((xs >> 6) & 3, true);
    }

    // KLD: each hlane handles one of the 16 latent dims (per half / batch).
    float kt;
    {
        float mu = mus[(size_t)b * E_DIM + h];
        float lv = lvs[(size_t)b * E_DIM + h];
        kt = 1.0f + lv - mu * mu - __expf(lv);
    }
    kt += __shfl_xor_sync(FULL, kt, 8, 16);
    kt += __shfl_xor_sync(FULL, kt, 4, 16);
    kt += __shfl_xor_sync(FULL, kt, 2, 16);
    kt += __shfl_xor_sync(FULL, kt, 1, 16);
    float kld = -0.5f * kt;

    if (h == 15) {
        float fin = fmaf(A64mm, FM64, fmaf(A64im, FI64, A64dm * FD64));
        g_loss[b] = -(logf(fin) + (float)ex_sum * 0.69314718055994531f) + kld;
    }

    // ── Fused deterministic final reduction (last-block-done) ──
    __threadfence();
    __syncthreads();
    if (threadIdx.x == 0) s_rank = atomicAdd(&g_ctr, 1);
    __syncthreads();
    if (s_rank == gridDim.x - 1) {
        __threadfence();
        float v = 0.0f;
        #pragma unroll
        for (int i = 0; i < B / 128; ++i)
            v += __ldcg(&g_loss[threadIdx.x + i * 128]);
        v += __shfl_xor_sync(FULL, v, 16);
        v += __shfl_xor_sync(FULL, v, 8);
        v += __shfl_xor_sync(FULL, v, 4);
        v += __shfl_xor_sync(FULL, v, 2);
        v += __shfl_xor_sync(FULL, v, 1);
        if (lane == 0) sw[wIn] = v;
        __syncthreads();
        if (threadIdx.x == 0) {
            out[0] = (sw[0] + sw[1] + sw[2] + sw[3]) * (1.0f / (float)B);
            g_ctr = 0;   // reset for next graph replay
        }
    }
}

extern "C" void kernel_launch(void* const* d_in, const int* in_sizes, int n_in,
                              void* d_out, int out_size)
{
    const int*   x   = (const int*)d_in[0];
    const float* a   = (const float*)d_in[1];
    const float* e   = (const float*)d_in[2];
    const float* mus = (const float*)d_in[3];
    const float* lvs = (const float*)d_in[4];

    // 2048 warps, 2 batch elements per warp, 4 warps per block.
    phmm_kernel<<<B / 8, 128>>>(x, a, e, mus, lvs, (float*)d_out);
}

// round 4
// speedup vs baseline: 1.4121x; 1.0670x over previous
#include <cuda_runtime.h>

#define FULL 0xffffffffu

constexpr int B = 4096;
constexpr int K = 64;
constexpr int L = 128;
constexpr int E_DIM = 16;

__device__ float g_loss[B];
__device__ unsigned g_ctr = 0;

typedef unsigned long long u64;

__device__ __forceinline__ u64 pk(float lo, float hi) {
    u64 r; asm("mov.b64 %0,{%1,%2};" : "=l"(r) : "f"(lo), "f"(hi)); return r;
}
__device__ __forceinline__ void upk(u64 v, float& lo, float& hi) {
    asm("mov.b64 {%0,%1},%2;" : "=f"(lo), "=f"(hi) : "l"(v));
}
__device__ __forceinline__ u64 fma2(u64 a, u64 b, u64 c) {
    u64 d; asm("fma.rn.f32x2 %0,%1,%2,%3;" : "=l"(d) : "l"(a), "l"(b), "l"(c)); return d;
}
__device__ __forceinline__ u64 mul2(u64 a, u64 b) {
    u64 d; asm("mul.rn.f32x2 %0,%1,%2;" : "=l"(d) : "l"(a), "l"(b)); return d;
}

// Wavefront-pipelined pHMM forward. Two batch elements per warp (16-lane
// halves). Lane h owns states {4h..4h+3}; lane 15 shadows state 64.
// At wall-iteration w, lane h processes ITS time step l = w - h, consuming
// lane h-1's same-step exports (v3 = fM'[4h], fd4 = fD'[4h]) produced at
// wall-iteration w-1. Per-lane power-of-2 exponent Ex; incoming values are
// realigned by 2^(E_sender - E_self). Rescale every 2 wall iterations
// (warp-uniform). Transition order: M2M,M2I,M2D,I2M,I2I,D2M,D2D.

#define ITER(WV, RESC, GUARD) do {                                             \
    float pv3 = __shfl_up_sync(FULL, v3x, 1, 16);                              \
    float pfd = __shfl_up_sync(FULL, fd4x, 1, 16);                             \
    int   pE  = __shfl_up_sync(FULL, Ex,  1, 16);                              \
    float4 ev = epb[nsym * 16 + h];         /* emission for own step l */      \
    { int nl = (WV) - h + 1;                 /* prefetch next step's symbol */ \
      nl = max(0, min(127, nl));                                               \
      nsym = rawx[nl] & 3; }                                                   \
    int dE = pE - Ex; dE = max(-126, min(126, dE));                            \
    float af = __uint_as_float((unsigned)(127 + dE) << 23);                    \
    float pv3a = (h == 0) ? 0.0f : pv3 * af;                                   \
    float pfda = (h == 0) ? 0.0f : pfd * af;                                   \
    u64 prev_a = fma2(Amm_a, FMa, fma2(Aim_a, FIa, mul2(Adm_a, FDa)));         \
    u64 prev_b = fma2(Amm_b, FMb, fma2(Aim_b, FIb, mul2(Adm_b, FDb)));         \
    u64 nFIa = fma2(AqMI_a, FMa, mul2(AqII_a, FIa));                           \
    u64 nFIb = fma2(AqMI_b, FMb, mul2(AqII_b, FIb));                           \
    float nFI64 = fmaf(Aq64MI, v3x, Aq64II * FI64);                            \
    float p0, p1, p2, p3; upk(prev_a, p0, p1); upk(prev_b, p2, p3);            \
    float v0 = ev.x * p0, v1 = ev.y * p1, v2 = ev.z * p2, nv3 = ev.w * p3;     \
    float fd0 = pfda;                                                          \
    float fd1 = fmaf(Add0, fd0, Amd0 * pv3a);                                  \
    float fd2 = fmaf(Add1, fd1, Amd1 * v0);                                    \
    float fd3 = fmaf(Add2, fd2, Amd2 * v1);                                    \
    float nfd4 = fmaf(Add3, fd3, Amd3 * v2);                                   \
    u64 nFMa = pk(pv3a, v0), nFMb = pk(v1, v2);                                \
    u64 nFDa = pk(fd0, fd1), nFDb = pk(fd2, fd3);                              \
    int exv = 0;                                                               \
    if (RESC) {                                                                \
        float m = fmaxf(fmaxf(pv3a, v0), fmaxf(v1, v2));                       \
        m = fmaxf(m, fmaxf(fmaxf(fd0, fd1), fmaxf(fd2, fd3)));                 \
        float g0, g1, g2, g3; upk(nFIa, g0, g1); upk(nFIb, g2, g3);            \
        m = fmaxf(m, fmaxf(fmaxf(g0, g1), fmaxf(g2, g3)));                     \
        m = fmaxf(m, fmaxf(nv3, fmaxf(nfd4, nFI64)));                          \
        exv = (int)((__float_as_uint(m) >> 23) & 255) - 127;                   \
        float sc = __uint_as_float((unsigned)(127 - exv) << 23);               \
        u64 s2 = pk(sc, sc);                                                   \
        nFMa = mul2(nFMa, s2); nFMb = mul2(nFMb, s2);                          \
        nFIa = mul2(nFIa, s2); nFIb = mul2(nFIb, s2);                          \
        nFDa = mul2(nFDa, s2); nFDb = mul2(nFDb, s2);                          \
        nFI64 *= sc; nv3 *= sc; nfd4 *= sc;                                    \
    }                                                                          \
    if (GUARD) {                                                               \
        bool act = (unsigned)((WV) - h) < 128u;                                \
        FMa = act ? nFMa : FMa;  FMb = act ? nFMb : FMb;                       \
        FIa = act ? nFIa : FIa;  FIb = act ? nFIb : FIb;                       \
        FDa = act ? nFDa : FDa;  FDb = act ? nFDb : FDb;                       \
        FI64 = act ? nFI64 : FI64;                                             \
        v3x  = act ? nv3  : v3x;                                               \
        fd4x = act ? nfd4 : fd4x;                                              \
        Ex   = act ? (Ex + exv) : Ex;                                          \
    } else {                                                                   \
        FMa = nFMa; FMb = nFMb; FIa = nFIa; FIb = nFIb;                        \
        FDa = nFDa; FDb = nFDb;                                                \
        FI64 = nFI64; v3x = nv3; fd4x = nfd4; Ex += exv;                       \
    }                                                                          \
} while (0)

__global__ __launch_bounds__(128) void phmm_kernel(
    const int*   __restrict__ x,
    const float* __restrict__ a,
    const float* __restrict__ e,
    const float* __restrict__ mus,
    const float* __restrict__ lvs,
    float*       __restrict__ out)
{
    const int warp = (blockIdx.x * blockDim.x + threadIdx.x) >> 5;
    const int lane = threadIdx.x & 31;
    const int half = lane >> 4;
    const int h    = lane & 15;
    const int wIn  = threadIdx.x >> 5;
    const int b = 2 * warp + half;

    __shared__ float4 sh_e[4 * 2 * 4 * 16];  // [warp][half][symbol][hlane]
    __shared__ int4   sh_x[4 * 2 * 32];      // [warp][half][128 ints]
    __shared__ float sw[4];
    __shared__ unsigned s_rank;

    const float* ab = a + (size_t)b * (K + 1) * 7;
    const int k0 = 4 * h;
    const float* A0 = ab + (k0 + 0) * 7;
    const float* A1 = ab + (k0 + 1) * 7;
    const float* A2 = ab + (k0 + 2) * 7;
    const float* A3 = ab + (k0 + 3) * 7;

    u64 Amm_a  = pk(__expf(A0[0]), __expf(A1[0]));
    u64 Amm_b  = pk(__expf(A2[0]), __expf(A3[0]));
    u64 AqMI_a = pk(0.25f * __expf(A0[1]), 0.25f * __expf(A1[1]));
    u64 AqMI_b = pk(0.25f * __expf(A2[1]), 0.25f * __expf(A3[1]));
    float Amd0 = __expf(A0[2]), Amd1 = __expf(A1[2]);
    float Amd2 = __expf(A2[2]), Amd3 = __expf(A3[2]);
    u64 Aim_a  = pk(__expf(A0[3]), __expf(A1[3]));
    u64 Aim_b  = pk(__expf(A2[3]), __expf(A3[3]));
    u64 AqII_a = pk(0.25f * __expf(A0[4]), 0.25f * __expf(A1[4]));
    u64 AqII_b = pk(0.25f * __expf(A2[4]), 0.25f * __expf(A3[4]));
    u64 Adm_a  = pk(__expf(A0[5]), __expf(A1[5]));
    u64 Adm_b  = pk(__expf(A2[5]), __expf(A3[5]));
    float Add0 = __expf(A0[6]), Add1 = __expf(A1[6]);
    float Add2 = __expf(A2[6]), Add3 = __expf(A3[6]);

    // Segment coefficients for the one-time init scan.
    float c2 = Add3;
    float c1 = Add3 * Add2;
    float c0 = c1 * Add1;
    float segB = c0 * Add0;

    const float* a64 = ab + K * 7;
    float A64mm  = __expf(a64[0]);
    float Aq64MI = 0.25f * __expf(a64[1]);
    float A64im  = __expf(a64[3]);
    float Aq64II = 0.25f * __expf(a64[4]);
    float A64dm  = __expf(a64[5]);

    // Emission LUT (conflict-free LDS.128): epb[sym*16+h] = exp(e[4h..4h+3][sym])
    const float4* e4 = (const float4*)(e + (size_t)b * K * 4);
    float4 e0 = e4[k0], e1 = e4[k0 + 1], e2 = e4[k0 + 2], e3 = e4[k0 + 3];
    float4* epb = sh_e + (size_t)((wIn * 2 + half) * 4) * 16;
    epb[0 * 16 + h] = make_float4(__expf(e0.x), __expf(e1.x), __expf(e2.x), __expf(e3.x));
    epb[1 * 16 + h] = make_float4(__expf(e0.y), __expf(e1.y), __expf(e2.y), __expf(e3.y));
    epb[2 * 16 + h] = make_float4(__expf(e0.z), __expf(e1.z), __expf(e2.z), __expf(e3.z));
    epb[3 * 16 + h] = make_float4(__expf(e0.w), __expf(e1.w), __expf(e2.w), __expf(e3.w));

    // Raw symbols to shared (lane h reads x[l] for its own skewed l).
    const int4* x4 = (const int4*)(x + (size_t)b * L);
    int4* xr4 = sh_x + (wIn * 2 + half) * 32;
    xr4[h]      = x4[h];
    xr4[h + 16] = x4[h + 16];
    const int* rawx = (const int*)xr4;

    // One-time Kogge-Stone weights + init fD chain (time-invariant part).
    float Bp0, Bp1, Bp2, Bp3;
    {
        float Bacc = segB;
        Bp0 = (h >= 1) ? Bacc : 0.0f;
        float o = __shfl_up_sync(FULL, Bacc, 1, 16); if (h >= 1) Bacc *= o;
        Bp1 = (h >= 2) ? Bacc : 0.0f;
        o = __shfl_up_sync(FULL, Bacc, 2, 16); if (h >= 2) Bacc *= o;
        Bp2 = (h >= 4) ? Bacc : 0.0f;
        o = __shfl_up_sync(FULL, Bacc, 4, 16); if (h >= 4) Bacc *= o;
        Bp3 = (h >= 8) ? Bacc : 0.0f;
    }

    // Initial state (l = 0 pending): fM[0]=1 rest 0; fI=0; fD via init scan.
    u64 FMa = pk((h == 0) ? 1.0f : 0.0f, 0.0f);
    u64 FMb = pk(0.0f, 0.0f);
    u64 FIa = pk(0.0f, 0.0f), FIb = pk(0.0f, 0.0f);
    float FI64 = 0.0f;
    float v3x = 0.0f;            // doubles as fM[64] shadow (init 0)
    float fd4x;                  // doubles as fD[64] shadow
    int Ex = 0;
    u64 FDa, FDb;
    {
        float fm0 = (h == 0) ? 1.0f : 0.0f;
        float u0 = Amd0 * fm0;
        float al = c0 * u0;
        float t_;
        t_ = __shfl_up_sync(FULL, al, 1, 16); al = fmaf(Bp0, t_, al);
        t_ = __shfl_up_sync(FULL, al, 2, 16); al = fmaf(Bp1, t_, al);
        t_ = __shfl_up_sync(FULL, al, 4, 16); al = fmaf(Bp2, t_, al);
        t_ = __shfl_up_sync(FULL, al, 8, 16); al = fmaf(Bp3, t_, al);
        float carry = __shfl_up_sync(FULL, al, 1, 16);
        if (h == 0) carry = 0.0f;
        float fd0 = carry;
        float fd1 = fmaf(Add0, fd0, u0);
        float fd2 = Add1 * fd1;
        float fd3 = Add2 * fd2;
        FDa = pk(fd0, fd1); FDb = pk(fd2, fd3);
        fd4x = al;               // fD[64] init
    }

    __syncthreads();             // shared LUTs + symbols visible

    int nsym = rawx[0] & 3;      // first-symbol prefetch (lane 0's l = 0)

    // ── ramp-in: w = 0..14 (guarded) ──
    #pragma unroll 1
    for (int w = 0; w < 15; ++w) {
        bool rs = (w & 1) == 1;
        ITER(w, rs, true);
    }
    // ── steady: w = 15..126 (all lanes active, rescale on odd w) ──
    #pragma unroll 1
    for (int wb = 15; wb < 127; wb += 2) {
        ITER(wb,     true,  false);
        ITER(wb + 1, false, false);
    }
    // w = 127 (odd → rescale), still all-active
    ITER(127, true, false);
    // ── ramp-out: w = 128..142 (guarded) ──
    #pragma unroll 1
    for (int w = 128; w < 143; ++w) {
        bool rs = (w & 1) == 1;
        ITER(w, rs, true);
    }

    // KLD: each hlane handles one latent dim for its batch.
    float kt;
    {
        float mu = mus[(size_t)b * E_DIM + h];
        float lv = lvs[(size_t)b * E_DIM + h];
        kt = 1.0f + lv - mu * mu - __expf(lv);
    }
    kt += __shfl_xor_sync(FULL, kt, 8, 16);
    kt += __shfl_xor_sync(FULL, kt, 4, 16);
    kt += __shfl_xor_sync(FULL, kt, 2, 16);
    kt += __shfl_xor_sync(FULL, kt, 1, 16);
    float kld = -0.5f * kt;

    if (h == 15) {
        // fM[64]=v3x, fI[64]=FI64, fD[64]=fd4x, all at scale 2^Ex.
        float fin = fmaf(A64mm, v3x, fmaf(A64im, FI64, A64dm * fd4x));
        g_loss[b] = -(logf(fin) + (float)Ex * 0.69314718055994531f) + kld;
    }

    // ── Fused deterministic final reduction (last-block-done) ──
    __threadfence();
    __syncthreads();
    if (threadIdx.x == 0) s_rank = atomicAdd(&g_ctr, 1);
    __syncthreads();
    if (s_rank == gridDim.x - 1) {
        __threadfence();
        float v = 0.0f;
        #pragma unroll
        for (int i = 0; i < B / 128; ++i)
            v += __ldcg(&g_loss[threadIdx.x + i * 128]);
        v += __shfl_xor_sync(FULL, v, 16);
        v += __shfl_xor_sync(FULL, v, 8);
        v += __shfl_xor_sync(FULL, v, 4);
        v += __shfl_xor_sync(FULL, v, 2);
        v += __shfl_xor_sync(FULL, v, 1);
        if (lane == 0) sw[wIn] = v;
        __syncthreads();
        if (threadIdx.x == 0) {
            out[0] = (sw[0] + sw[1] + sw[2] + sw[3]) * (1.0f / (float)B);
            g_ctr = 0;   // reset for next graph replay
        }
    }
}

extern "C" void kernel_launch(void* const* d_in, const int* in_sizes, int n_in,
                              void* d_out, int out_size)
{
    const int*   x   = (const int*)d_in[0];
    const float* a   = (const float*)d_in[1];
    const float* e   = (const float*)d_in[2];
    const float* mus = (const float*)d_in[3];
    const float* lvs = (const float*)d_in[4];

    phmm_kernel<<<B / 8, 128>>>(x, a, e, mus, lvs, (float*)d_out);
}

// round 6
// speedup vs baseline: 1.5375x; 1.0888x over previous
#include <cuda_runtime.h>

#define FULL 0xffffffffu

constexpr int B = 4096;
constexpr int K = 64;
constexpr int L = 128;
constexpr int E_DIM = 16;

__device__ float g_loss[B];
__device__ unsigned g_ctr = 0;

typedef unsigned long long u64;

__device__ __forceinline__ u64 pk(float lo, float hi) {
    u64 r; asm("mov.b64 %0,{%1,%2};" : "=l"(r) : "f"(lo), "f"(hi)); return r;
}
__device__ __forceinline__ void upk(u64 v, float& lo, float& hi) {
    asm("mov.b64 {%0,%1},%2;" : "=f"(lo), "=f"(hi) : "l"(v));
}
__device__ __forceinline__ u64 fma2(u64 a, u64 b, u64 c) {
    u64 d; asm("fma.rn.f32x2 %0,%1,%2,%3;" : "=l"(d) : "l"(a), "l"(b), "l"(c)); return d;
}
__device__ __forceinline__ u64 mul2(u64 a, u64 b) {
    u64 d; asm("mul.rn.f32x2 %0,%1,%2;" : "=l"(d) : "l"(a), "l"(b)); return d;
}

// Wavefront-pipelined pHMM forward. Two batch elements per warp (16-lane
// halves). Lane h owns states {4h..4h+3}; lane 15 shadows state 64.
// At wall-iteration w, lane h processes ITS time step l = w - h, consuming
// lane h-1's same-step exports (v3 = fM'[4h], fd4 = fD'[4h]) produced at
// wall-iteration w-1. Per-lane power-of-2 exponent Ex; incoming values are
// realigned by 2^(E_sender - E_self). Rescale every 4 wall iterations
// (warp-uniform, (w & 3) == 3). Transitions: M2M,M2I,M2D,I2M,I2I,D2M,D2D.

#define ITER(WV, RESC, GUARD) do {                                             \
    float pv3 = __shfl_up_sync(FULL, v3x, 1, 16);                              \
    float pfd = __shfl_up_sync(FULL, fd4x, 1, 16);                             \
    int   pE  = __shfl_up_sync(FULL, Ex,  1, 16);                              \
    float4 ev = *(const float4*)(epbh + nsymB);  /* conflict-free LDS.128 */   \
    nsymB = rawp[WV];                         /* prefetch next step (x<<8) */  \
    int dE = pE - Ex; dE = max(-126, min(126, dE));                            \
    float af = __uint_as_float((unsigned)(127 + dE) << 23);                    \
    float pv3a = (h == 0) ? 0.0f : pv3 * af;                                   \
    float pfda = (h == 0) ? 0.0f : pfd * af;                                   \
    u64 prev_a = fma2(Amm_a, FMa, fma2(Aim_a, FIa, mul2(Adm_a, FDa)));         \
    u64 prev_b = fma2(Amm_b, FMb, fma2(Aim_b, FIb, mul2(Adm_b, FDb)));         \
    u64 nFIa = fma2(AqMI_a, FMa, mul2(AqII_a, FIa));                           \
    u64 nFIb = fma2(AqMI_b, FMb, mul2(AqII_b, FIb));                           \
    float nFI64 = fmaf(Aq64MI, v3x, Aq64II * FI64);                            \
    float p0, p1, p2, p3; upk(prev_a, p0, p1); upk(prev_b, p2, p3);            \
    float v0 = ev.x * p0, v1 = ev.y * p1, v2 = ev.z * p2, nv3 = ev.w * p3;     \
    float fd0 = pfda;                                                          \
    float fd1 = fmaf(Add0, fd0, Amd0 * pv3a);                                  \
    float fd2 = fmaf(Add1, fd1, Amd1 * v0);                                    \
    float fd3 = fmaf(Add2, fd2, Amd2 * v1);                                    \
    float nfd4 = fmaf(Add3, fd3, Amd3 * v2);                                   \
    u64 nFMa = pk(pv3a, v0), nFMb = pk(v1, v2);                                \
    u64 nFDa = pk(fd0, fd1), nFDb = pk(fd2, fd3);                              \
    int exv = 0;                                                               \
    if (RESC) {                                                                \
        float m = fmaxf(fmaxf(pv3a, v0), fmaxf(v1, v2));                       \
        m = fmaxf(m, fmaxf(fmaxf(fd0, fd1), fmaxf(fd2, fd3)));                 \
        float g0, g1, g2, g3; upk(nFIa, g0, g1); upk(nFIb, g2, g3);            \
        m = fmaxf(m, fmaxf(fmaxf(g0, g1), fmaxf(g2, g3)));                     \
        m = fmaxf(m, fmaxf(nv3, fmaxf(nfd4, nFI64)));                          \
        exv = (int)((__float_as_uint(m) >> 23) & 255) - 127;                   \
        float sc = __uint_as_float((unsigned)(127 - exv) << 23);               \
        u64 s2 = pk(sc, sc);                                                   \
        nFMa = mul2(nFMa, s2); nFMb = mul2(nFMb, s2);                          \
        nFIa = mul2(nFIa, s2); nFIb = mul2(nFIb, s2);                          \
        nFDa = mul2(nFDa, s2); nFDb = mul2(nFDb, s2);                          \
        nFI64 *= sc; nv3 *= sc; nfd4 *= sc;                                    \
    }                                                                          \
    if (GUARD) {                                                               \
        bool act = (unsigned)((WV) - h) < 128u;                                \
        FMa = act ? nFMa : FMa;  FMb = act ? nFMb : FMb;                       \
        FIa = act ? nFIa : FIa;  FIb = act ? nFIb : FIb;                       \
        FDa = act ? nFDa : FDa;  FDb = act ? nFDb : FDb;                       \
        FI64 = act ? nFI64 : FI64;                                             \
        v3x  = act ? nv3  : v3x;                                               \
        fd4x = act ? nfd4 : fd4x;                                              \
        Ex   = act ? (Ex + exv) : Ex;                                          \
    } else {                                                                   \
        FMa = nFMa; FMb = nFMb; FIa = nFIa; FIb = nFIb;                        \
        FDa = nFDa; FDb = nFDb;                                                \
        FI64 = nFI64; v3x = nv3; fd4x = nfd4; Ex += exv;                       \
    }                                                                          \
} while (0)

__global__ __launch_bounds__(64) void phmm_kernel(
    const int*   __restrict__ x,
    const float* __restrict__ a,
    const float* __restrict__ e,
    const float* __restrict__ mus,
    const float* __restrict__ lvs,
    float*       __restrict__ out)
{
    const int lane = threadIdx.x & 31;
    const int half = lane >> 4;
    const int h    = lane & 15;
    const int wIn  = threadIdx.x >> 5;
    const int warp = blockIdx.x * 2 + wIn;
    const int b = 2 * warp + half;

    __shared__ float4 sh_e[2 * 2 * 4 * 16];  // [warp][half][symbol][hlane]
    __shared__ int    sh_x[2 * 2 * 160];     // padded symbols (×256 pre-scaled)
    __shared__ float sw[2];
    __shared__ unsigned s_rank;

    const float* ab = a + (size_t)b * (K + 1) * 7;
    const int k0 = 4 * h;
    const float* A0 = ab + (k0 + 0) * 7;
    const float* A1 = ab + (k0 + 1) * 7;
    const float* A2 = ab + (k0 + 2) * 7;
    const float* A3 = ab + (k0 + 3) * 7;

    u64 Amm_a  = pk(__expf(A0[0]), __expf(A1[0]));
    u64 Amm_b  = pk(__expf(A2[0]), __expf(A3[0]));
    u64 AqMI_a = pk(0.25f * __expf(A0[1]), 0.25f * __expf(A1[1]));
    u64 AqMI_b = pk(0.25f * __expf(A2[1]), 0.25f * __expf(A3[1]));
    float Amd0 = __expf(A0[2]), Amd1 = __expf(A1[2]);
    float Amd2 = __expf(A2[2]), Amd3 = __expf(A3[2]);
    u64 Aim_a  = pk(__expf(A0[3]), __expf(A1[3]));
    u64 Aim_b  = pk(__expf(A2[3]), __expf(A3[3]));
    u64 AqII_a = pk(0.25f * __expf(A0[4]), 0.25f * __expf(A1[4]));
    u64 AqII_b = pk(0.25f * __expf(A2[4]), 0.25f * __expf(A3[4]));
    u64 Adm_a  = pk(__expf(A0[5]), __expf(A1[5]));
    u64 Adm_b  = pk(__expf(A2[5]), __expf(A3[5]));
    float Add0 = __expf(A0[6]), Add1 = __expf(A1[6]);
    float Add2 = __expf(A2[6]), Add3 = __expf(A3[6]);

    // Segment coefficients for the one-time init scan.
    float c2 = Add3;
    float c1 = Add3 * Add2;
    float c0 = c1 * Add1;
    float segB = c0 * Add0;

    const float* a64 = ab + K * 7;
    float A64mm  = __expf(a64[0]);
    float Aq64MI = 0.25f * __expf(a64[1]);
    float A64im  = __expf(a64[3]);
    float Aq64II = 0.25f * __expf(a64[4]);
    float A64dm  = __expf(a64[5]);

    // Emission LUT (conflict-free LDS.128): epb[sym*16+h] = exp(e[4h..4h+3][sym])
    const float4* e4 = (const float4*)(e + (size_t)b * K * 4);
    float4 e0 = e4[k0], e1 = e4[k0 + 1], e2 = e4[k0 + 2], e3 = e4[k0 + 3];
    float4* epb = sh_e + (size_t)((wIn * 2 + half) * 4) * 16;
    epb[0 * 16 + h] = make_float4(__expf(e0.x), __expf(e1.x), __expf(e2.x), __expf(e3.x));
    epb[1 * 16 + h] = make_float4(__expf(e0.y), __expf(e1.y), __expf(e2.y), __expf(e3.y));
    epb[2 * 16 + h] = make_float4(__expf(e0.z), __expf(e1.z), __expf(e2.z), __expf(e3.z));
    epb[3 * 16 + h] = make_float4(__expf(e0.w), __expf(e1.w), __expf(e2.w), __expf(e3.w));
    const char* epbh = (const char*)epb + h * 16;

    // Symbols to shared, pre-scaled by 256 (byte offset into the LUT) and
    // padded by 16 entries front/back so the skewed prefetch never clamps.
    const int4* x4 = (const int4*)(x + (size_t)b * L);
    int* xr = sh_x + (wIn * 2 + half) * 160;
    {
        int4 xa = x4[h], xb = x4[h + 16];
        xr[h] = 0; xr[144 + h] = 0;
        xr[16 + 4 * h + 0] = xa.x << 8;
        xr[16 + 4 * h + 1] = xa.y << 8;
        xr[16 + 4 * h + 2] = xa.z << 8;
        xr[16 + 4 * h + 3] = xa.w << 8;
        xr[80 + 4 * h + 0] = xb.x << 8;
        xr[80 + 4 * h + 1] = xb.y << 8;
        xr[80 + 4 * h + 2] = xb.z << 8;
        xr[80 + 4 * h + 3] = xb.w << 8;
    }
    const int* rawp = xr + 17 - h;   // rawp[w] = x[w - h + 1] << 8

    // One-time Kogge-Stone weights + init fD chain.
    float Bp0, Bp1, Bp2, Bp3;
    {
        float Bacc = segB;
        Bp0 = (h >= 1) ? Bacc : 0.0f;
        float o = __shfl_up_sync(FULL, Bacc, 1, 16); if (h >= 1) Bacc *= o;
        Bp1 = (h >= 2) ? Bacc : 0.0f;
        o = __shfl_up_sync(FULL, Bacc, 2, 16); if (h >= 2) Bacc *= o;
        Bp2 = (h >= 4) ? Bacc : 0.0f;
        o = __shfl_up_sync(FULL, Bacc, 4, 16); if (h >= 4) Bacc *= o;
        Bp3 = (h >= 8) ? Bacc : 0.0f;
    }

    // Initial state: fM[0]=1 rest 0; fI=0; fD via init scan.
    u64 FMa = pk((h == 0) ? 1.0f : 0.0f, 0.0f);
    u64 FMb = pk(0.0f, 0.0f);
    u64 FIa = pk(0.0f, 0.0f), FIb = pk(0.0f, 0.0f);
    float FI64 = 0.0f;
    float v3x = 0.0f;            // fM[4h+4] export / fM[64] shadow
    float fd4x;                  // fD[4h+4] export / fD[64] shadow
    int Ex = 0;
    u64 FDa, FDb;
    {
        float fm0 = (h == 0) ? 1.0f : 0.0f;
        float u0 = Amd0 * fm0;
        float al = c0 * u0;
        float t_;
        t_ = __shfl_up_sync(FULL, al, 1, 16); al = fmaf(Bp0, t_, al);
        t_ = __shfl_up_sync(FULL, al, 2, 16); al = fmaf(Bp1, t_, al);
        t_ = __shfl_up_sync(FULL, al, 4, 16); al = fmaf(Bp2, t_, al);
        t_ = __shfl_up_sync(FULL, al, 8, 16); al = fmaf(Bp3, t_, al);
        float carry = __shfl_up_sync(FULL, al, 1, 16);
        if (h == 0) carry = 0.0f;
        float fd0 = carry;
        float fd1 = fmaf(Add0, fd0, u0);
        float fd2 = Add1 * fd1;
        float fd3 = Add2 * fd2;
        FDa = pk(fd0, fd1); FDb = pk(fd2, fd3);
        fd4x = al;
    }

    __syncthreads();             // shared LUTs + symbols visible

    int nsymB = rawp[h - 1];     // lane's first symbol: x[0] << 8

    // ── ramp-in: w = 0..14 (guarded), rescale on (w & 3) == 3 ──
    #pragma unroll 1
    for (int w = 0; w < 15; ++w) {
        bool rs = (w & 3) == 3;
        ITER(w, rs, true);
    }
    // ── steady: w = 15..126 (all lanes active); rescale at group head ──
    #pragma unroll 1
    for (int wb = 15; wb < 127; wb += 4) {
        ITER(wb,     true,  false);     // wb ≡ 3 (mod 4)
        ITER(wb + 1, false, false);
        ITER(wb + 2, false, false);
        ITER(wb + 3, false, false);
    }
    ITER(127, true, false);             // 127 & 3 == 3
    // ── ramp-out: w = 128..142 (guarded) ──
    #pragma unroll 1
    for (int w = 128; w < 143; ++w) {
        bool rs = (w & 3) == 3;
        ITER(w, rs, true);
    }

    // KLD: each hlane handles one latent dim for its batch.
    float kt;
    {
        float mu = mus[(size_t)b * E_DIM + h];
        float lv = lvs[(size_t)b * E_DIM + h];
        kt = 1.0f + lv - mu * mu - __expf(lv);
    }
    kt += __shfl_xor_sync(FULL, kt, 8, 16);
    kt += __shfl_xor_sync(FULL, kt, 4, 16);
    kt += __shfl_xor_sync(FULL, kt, 2, 16);
    kt += __shfl_xor_sync(FULL, kt, 1, 16);
    float kld = -0.5f * kt;

    if (h == 15) {
        // fM[64]=v3x, fI[64]=FI64, fD[64]=fd4x, all at scale 2^Ex.
        float fin = fmaf(A64mm, v3x, fmaf(A64im, FI64, A64dm * fd4x));
        g_loss[b] = -(logf(fin) + (float)Ex * 0.69314718055994531f) + kld;
    }

    // ── Fused deterministic final reduction (last-block-done) ──
    __threadfence();
    __syncthreads();
    if (threadIdx.x == 0) s_rank = atomicAdd(&g_ctr, 1);
    __syncthreads();
    if (s_rank == gridDim.x - 1) {
        __threadfence();
        float v = 0.0f;
        #pragma unroll
        for (int i = 0; i < B / 64; ++i)
            v += __ldcg(&g_loss[threadIdx.x + i * 64]);
        v += __shfl_xor_sync(FULL, v, 16);
        v += __shfl_xor_sync(FULL, v, 8);
        v += __shfl_xor_sync(FULL, v, 4);
        v += __shfl_xor_sync(FULL, v, 2);
        v += __shfl_xor_sync(FULL, v, 1);
        if (lane == 0) sw[wIn] = v;
        __syncthreads();
        if (threadIdx.x == 0) {
            out[0] = (sw[0] + sw[1]) * (1.0f / (float)B);
            g_ctr = 0;   // reset for next graph replay
        }
    }
}

extern "C" void kernel_launch(void* const* d_in, const int* in_sizes, int n_in,
                              void* d_out, int out_size)
{
    const int*   x   = (const int*)d_in[0];
    const float* a   = (const float*)d_in[1];
    const float* e   = (const float*)d_in[2];
    const float* mus = (const float*)d_in[3];
    const float* lvs = (const float*)d_in[4];

    // 1024 blocks × 2 warps × 2 batches/warp = 4096 batch elements.
    phmm_kernel<<<B / 4, 64>>>(x, a, e, mus, lvs, (float*)d_out);
}